// round 9
// baseline (speedup 1.0000x reference)
#include <cuda_runtime.h>
#include <cuda_bf16.h>
#include <cstdint>

// Problem shape
#define NB  16
#define NL  2048
#define NH  768
#define ND  64
#define CK  128
#define NCH (NL/CK)       // 16
#define HT  128
#define NHT (NH/HT)       // 6
#define DH  (ND*NH)       // 49152

typedef unsigned int u32;

// Scratch planes (bf16 hi/lo; ~92 MB total)
#define NE (NB*NL*ND)
__device__ __align__(16) __nv_bfloat16 cEh [NE], cEl [NE];                   // E  [t][d]
__device__ __align__(16) __nv_bfloat16 cFh [NE], cFl [NE];                   // Fp [t][d]
__device__ __align__(16) __nv_bfloat16 cEhT[NB*ND*NL],    cElT[NB*ND*NL];    // E^T [b][d][j]
__device__ __align__(16) __nv_bfloat16 cShT[NB*NCH*CK*CK],cSlT[NB*NCH*CK*CK];// S^T [i][j] masked
__device__ __align__(16) __nv_bfloat16 cMh [NB*NCH*DH],   cMl [NB*NCH*DH];   // M  [d][h]

// ---------------------------------------------------------------------------
// helpers
// ---------------------------------------------------------------------------
__device__ __forceinline__ u32 smem_u32(const void* p) {
    u32 a;
    asm("{ .reg .u64 t; cvta.to.shared.u64 t, %1; cvt.u32.u64 %0, t; }" : "=r"(a) : "l"(p));
    return a;
}
__device__ __forceinline__ u32 packbf(__nv_bfloat16 a, __nv_bfloat16 b) {
    __nv_bfloat162 t(a, b);
    return *reinterpret_cast<u32*>(&t);
}
__device__ __forceinline__ void splitpack(float a, float b, u32& hi, u32& lo) {
    __nv_bfloat16 ah = __float2bfloat16(a);
    __nv_bfloat16 bh = __float2bfloat16(b);
    __nv_bfloat16 al = __float2bfloat16(a - __bfloat162float(ah));
    __nv_bfloat16 bl = __float2bfloat16(b - __bfloat162float(bh));
    hi = packbf(ah, bh);
    lo = packbf(al, bl);
}
__device__ __forceinline__ float2 bf2f(u32 w) {
    __nv_bfloat162 t = *reinterpret_cast<__nv_bfloat162*>(&w);
    return make_float2(__bfloat162float(t.x), __bfloat162float(t.y));
}
__device__ __forceinline__ void cpa(u32 dst, const void* src) {
    asm volatile("cp.async.ca.shared.global [%0], [%1], 16;" :: "r"(dst), "l"(src));
}
#define CP_COMMIT() asm volatile("cp.async.commit_group;" ::: "memory")
#define CP_WAIT0()  asm volatile("cp.async.wait_group 0;" ::: "memory")

__device__ __forceinline__ void ldsm4t(u32* r, u32 addr) {
    asm volatile("ldmatrix.sync.aligned.m8n8.x4.trans.shared.b16 {%0,%1,%2,%3}, [%4];"
        : "=r"(r[0]), "=r"(r[1]), "=r"(r[2]), "=r"(r[3]) : "r"(addr));
}
__device__ __forceinline__ void mma16816(float* d, const u32* a, const u32* b) {
    asm volatile("mma.sync.aligned.m16n8k16.row.col.f32.bf16.bf16.f32 "
        "{%0,%1,%2,%3}, {%4,%5,%6,%7}, {%8,%9}, {%0,%1,%2,%3};"
        : "+f"(d[0]), "+f"(d[1]), "+f"(d[2]), "+f"(d[3])
        : "r"(a[0]), "r"(a[1]), "r"(a[2]), "r"(a[3]), "r"(b[0]), "r"(b[1]));
}

// ---------------------------------------------------------------------------
// K0: embedding gather + Fp = (l+1) * E @ w ; emits E/Fp hi-lo planes
// ---------------------------------------------------------------------------
__global__ void k_embed(const void* __restrict__ xraw,
                        const float* __restrict__ ae,
                        const float* __restrict__ w)
{
    __shared__ float sW[ND][ND];
    __shared__ float sE[4][ND];

    int tid = threadIdx.x;

    // Detect index dtype: int64 (odd 32-bit words all zero) vs int32.
    const int* xi = (const int*)xraw;
    int oddw = xi[((tid & 63) << 1) + 1];
    int is64 = __syncthreads_and(oddw == 0);

    for (int i = tid; i < ND * ND; i += 256)
        ((float*)sW)[i] = w[i];

    int q = tid >> 6;
    int d = tid & 63;
    int t = blockIdx.x * 4 + q;
    int l = t & (NL - 1);

    long long v;
    if (is64) v = ((const long long*)xraw)[t];
    else      v = (long long)xi[t];

    float e = ae[v * ND + d];
    sE[q][d] = e;
    size_t td = (size_t)t * ND + d;
    {
        float ep = __shfl_xor_sync(0xffffffffu, e, 1);
        if (!(d & 1)) {
            u32 hw, lw; splitpack(e, ep, hw, lw);
            *(u32*)&cEh[td] = hw;
            *(u32*)&cEl[td] = lw;
        }
    }
    __syncthreads();

    float acc = 0.f;
    #pragma unroll
    for (int k = 0; k < ND; k++)
        acc += sE[q][k] * sW[k][d];

    float fp = (float)(l + 1) * acc;
    {
        float fpp = __shfl_xor_sync(0xffffffffu, fp, 1);
        if (!(d & 1)) {
            u32 hw, lw; splitpack(fp, fpp, hw, lw);
            *(u32*)&cFh[td] = hw;
            *(u32*)&cFl[td] = lw;
        }
    }
}

// ---------------------------------------------------------------------------
// K1b: intra-chunk scores (scalar fp32); emits masked S^T planes + E^T planes
// ---------------------------------------------------------------------------
__global__ void k_scores()
{
    __shared__ float sEt[32][CK];
    __shared__ float sFt[32][CK];

    int tid = threadIdx.x;
    int c = blockIdx.x, b = blockIdx.y;

    size_t base = ((size_t)b * NL + c * CK) * ND;
    int tj = tid & 15;
    int ti = tid >> 4;

    float acc[8][8];
    #pragma unroll
    for (int r = 0; r < 8; r++)
        #pragma unroll
        for (int s = 0; s < 8; s++) acc[r][s] = 0.f;

    for (int dt = 0; dt < ND; dt += 32) {
        int f4 = tid & 7, r0 = tid >> 3;
        #pragma unroll
        for (int rep = 0; rep < 4; rep++) {
            int row = r0 + rep * 32;
            size_t o = base + (size_t)row * ND + dt + f4 * 4;
            uint2 vh = *(const uint2*)(cEh + o);
            uint2 vl = *(const uint2*)(cEl + o);
            float2 p0 = bf2f(vh.x), p1 = bf2f(vh.y), q0 = bf2f(vl.x), q1 = bf2f(vl.y);
            sEt[f4*4+0][row] = p0.x + q0.x; sEt[f4*4+1][row] = p0.y + q0.y;
            sEt[f4*4+2][row] = p1.x + q1.x; sEt[f4*4+3][row] = p1.y + q1.y;
            uint2 uh = *(const uint2*)(cFh + o);
            uint2 ul = *(const uint2*)(cFl + o);
            float2 a0 = bf2f(uh.x), a1 = bf2f(uh.y), b0 = bf2f(ul.x), b1 = bf2f(ul.y);
            sFt[f4*4+0][row] = a0.x + b0.x; sFt[f4*4+1][row] = a0.y + b0.y;
            sFt[f4*4+2][row] = a1.x + b1.x; sFt[f4*4+3][row] = a1.y + b1.y;
        }
        __syncthreads();

        // emit E^T planes for this d-slab: rows d = dt+r, 128 j cols
        {
            int r = tid >> 3, c8 = tid & 7;
            float4 v0 = *(const float4*)&sEt[r][c8*16];
            float4 v1 = *(const float4*)&sEt[r][c8*16 + 4];
            float4 v2 = *(const float4*)&sEt[r][c8*16 + 8];
            float4 v3 = *(const float4*)&sEt[r][c8*16 + 12];
            u32 h0,l0,h1,l1,h2,l2,h3,l3,h4,l4,h5,l5,h6,l6,h7,l7;
            splitpack(v0.x, v0.y, h0, l0); splitpack(v0.z, v0.w, h1, l1);
            splitpack(v1.x, v1.y, h2, l2); splitpack(v1.z, v1.w, h3, l3);
            splitpack(v2.x, v2.y, h4, l4); splitpack(v2.z, v2.w, h5, l5);
            splitpack(v3.x, v3.y, h6, l6); splitpack(v3.z, v3.w, h7, l7);
            size_t o = (size_t)b * ND * NL + (size_t)(dt + r) * NL + (size_t)c * CK + c8 * 16;
            *(uint4*)(cEhT + o)     = make_uint4(h0, h1, h2, h3);
            *(uint4*)(cEhT + o + 8) = make_uint4(h4, h5, h6, h7);
            *(uint4*)(cElT + o)     = make_uint4(l0, l1, l2, l3);
            *(uint4*)(cElT + o + 8) = make_uint4(l4, l5, l6, l7);
        }

        #pragma unroll 8
        for (int kk = 0; kk < 32; kk++) {
            float4 a0 = *(const float4*)&sEt[kk][tj*8];
            float4 a1 = *(const float4*)&sEt[kk][tj*8 + 4];
            float4 b0 = *(const float4*)&sFt[kk][ti*8];
            float4 b1 = *(const float4*)&sFt[kk][ti*8 + 4];
            float av[8] = {a0.x,a0.y,a0.z,a0.w,a1.x,a1.y,a1.z,a1.w};
            float bv[8] = {b0.x,b0.y,b0.z,b0.w,b1.x,b1.y,b1.z,b1.w};
            #pragma unroll
            for (int r = 0; r < 8; r++)
                #pragma unroll
                for (int s = 0; s < 8; s++)
                    acc[r][s] += av[r] * bv[s];
        }
        __syncthreads();
    }

    // emit masked S^T planes: row i, cols j
    size_t ST0 = (size_t)(b * NCH + c) * CK * CK;
    #pragma unroll
    for (int s = 0; s < 8; s++) {
        int i = ti * 8 + s;
        u32 hw[4], lw[4];
        #pragma unroll
        for (int p = 0; p < 4; p++) {
            int j0 = tj * 8 + 2 * p;
            float a  = (i < j0)     ? acc[2*p][s]     : 0.f;
            float bb = (i < j0 + 1) ? acc[2*p + 1][s] : 0.f;
            splitpack(a, bb, hw[p], lw[p]);
        }
        size_t o = ST0 + (size_t)i * CK + tj * 8;
        *(uint4*)(cShT + o) = make_uint4(hw[0], hw[1], hw[2], hw[3]);
        *(uint4*)(cSlT + o) = make_uint4(lw[0], lw[1], lw[2], lw[3]);
    }
}

// ---------------------------------------------------------------------------
// K1a (mma, pipelined): M[d][h] = sum_i Fp[i][d] * X[i][h]; 4 stages of k=32
// ---------------------------------------------------------------------------
#define KO_ST  24576
#define KO_AL  4096
#define KO_BH  8192
#define KO_BL  16384
#define KO_TOT (2*KO_ST)

__global__ void __launch_bounds__(256, 1) k_outer_mma(const float* __restrict__ bx)
{
    extern __shared__ char sm[];
    u32 smb = smem_u32(sm);
    int tid = threadIdx.x, wid = tid >> 5, ln = tid & 31;
    int ht = blockIdx.x, c = blockIdx.y, b = blockIdx.z;
    int h0 = ht * HT;
    int mw = (wid >> 2) * 32;
    int nw = (wid & 3) * 32;

    size_t fB = ((size_t)b * NL + c * CK) * ND;
    const float* Xg = bx + ((size_t)b * NL + c * CK) * NH + h0;

    float acc[2][4][4];
    #pragma unroll
    for (int i = 0; i < 2; i++)
        #pragma unroll
        for (int j = 0; j < 4; j++)
            #pragma unroll
            for (int k = 0; k < 4; k++) acc[i][j][k] = 0.f;

    // prologue: stage 0
    {
        int r = tid >> 3, c8 = tid & 7;
        u32 off = r * 128 + ((c8 ^ (r & 7)) << 4);
        size_t o = fB + (size_t)r * ND + c8 * 8;
        cpa(smb + off, cFh + o);
        cpa(smb + KO_AL + off, cFl + o);
        CP_COMMIT();
        #pragma unroll
        for (int it = 0; it < 2; it++) {
            int idx = tid + it * 256, rr = idx >> 4, cc = idx & 15;
            const float* p = Xg + (size_t)rr * NH + cc * 8;
            float4 v0 = *(const float4*)p;
            float4 v1 = *(const float4*)(p + 4);
            u32 h0w,l0w,h1w,l1w,h2w,l2w,h3w,l3w;
            splitpack(v0.x, v0.y, h0w, l0w); splitpack(v0.z, v0.w, h1w, l1w);
            splitpack(v1.x, v1.y, h2w, l2w); splitpack(v1.z, v1.w, h3w, l3w);
            u32 boff = rr * 256 + ((cc ^ (rr & 7)) << 4);
            *(uint4*)(sm + KO_BH + boff) = make_uint4(h0w, h1w, h2w, h3w);
            *(uint4*)(sm + KO_BL + boff) = make_uint4(l0w, l1w, l2w, l3w);
        }
    }

    for (int s = 0; s < 4; s++) {
        CP_WAIT0();
        __syncthreads();
        u32 cur = smb + (s & 1) * KO_ST;
        char* nxtp = sm + ((s + 1) & 1) * KO_ST;
        u32 nxt = smb + ((s + 1) & 1) * KO_ST;
        float4 xr[4];
        if (s < 3) {
            int s1 = s + 1;
            int r = tid >> 3, c8 = tid & 7;
            u32 off = r * 128 + ((c8 ^ (r & 7)) << 4);
            size_t o = fB + (size_t)(s1 * 32 + r) * ND + c8 * 8;
            cpa(nxt + off, cFh + o);
            cpa(nxt + KO_AL + off, cFl + o);
            CP_COMMIT();
            const float* xs = Xg + (size_t)(s1 * 32) * NH;
            #pragma unroll
            for (int it = 0; it < 2; it++) {
                int idx = tid + it * 256, rr = idx >> 4, cc = idx & 15;
                const float* p = xs + (size_t)rr * NH + cc * 8;
                xr[it*2]     = *(const float4*)p;
                xr[it*2 + 1] = *(const float4*)(p + 4);
            }
        }

        #pragma unroll
        for (int ks = 0; ks < 2; ks++) {
            u32 ah[2][4], al[2][4], bh[2][4], bl[2][4];
            int q = ln >> 3;
            #pragma unroll
            for (int mt = 0; mt < 2; mt++) {
                int r = ks * 16 + (q >> 1) * 8 + (ln & 7);
                int mc = (mw + mt * 16 + (q & 1) * 8) >> 3;
                u32 off = cur + r * 128 + ((mc ^ (r & 7)) << 4);
                ldsm4t(ah[mt], off);
                ldsm4t(al[mt], off + KO_AL);
            }
            #pragma unroll
            for (int nt2 = 0; nt2 < 2; nt2++) {
                int r = ks * 16 + (q & 1) * 8 + (ln & 7);
                int nc = (nw + nt2 * 16 + (q >> 1) * 8) >> 3;
                u32 off = cur + KO_BH + r * 256 + ((nc ^ (r & 7)) << 4);
                ldsm4t(bh[nt2], off);
                ldsm4t(bl[nt2], off + (KO_BL - KO_BH));
            }
            #pragma unroll
            for (int mt = 0; mt < 2; mt++)
                #pragma unroll
                for (int nt2 = 0; nt2 < 2; nt2++) {
                    mma16816(acc[mt][nt2*2],   ah[mt], &bh[nt2][0]);
                    mma16816(acc[mt][nt2*2+1], ah[mt], &bh[nt2][2]);
                    mma16816(acc[mt][nt2*2],   ah[mt], &bl[nt2][0]);
                    mma16816(acc[mt][nt2*2+1], ah[mt], &bl[nt2][2]);
                    mma16816(acc[mt][nt2*2],   al[mt], &bh[nt2][0]);
                    mma16816(acc[mt][nt2*2+1], al[mt], &bh[nt2][2]);
                }
        }

        if (s < 3) {
            #pragma unroll
            for (int it = 0; it < 2; it++) {
                int idx = tid + it * 256, rr = idx >> 4, cc = idx & 15;
                float4 v0 = xr[it*2], v1 = xr[it*2 + 1];
                u32 h0w,l0w,h1w,l1w,h2w,l2w,h3w,l3w;
                splitpack(v0.x, v0.y, h0w, l0w); splitpack(v0.z, v0.w, h1w, l1w);
                splitpack(v1.x, v1.y, h2w, l2w); splitpack(v1.z, v1.w, h3w, l3w);
                u32 boff = rr * 256 + ((cc ^ (rr & 7)) << 4);
                *(uint4*)(nxtp + KO_BH + boff) = make_uint4(h0w, h1w, h2w, h3w);
                *(uint4*)(nxtp + KO_BL + boff) = make_uint4(l0w, l1w, l2w, l3w);
            }
        }
    }

    // epilogue: write M planes (hi/lo)
    size_t mB = (size_t)(b * NCH + c) * DH;
    #pragma unroll
    for (int mt = 0; mt < 2; mt++)
        #pragma unroll
        for (int half = 0; half < 2; half++) {
            int d = mw + mt * 16 + (ln >> 2) + half * 8;
            #pragma unroll
            for (int nt = 0; nt < 4; nt++) {
                int h = h0 + nw + nt * 8 + (ln & 3) * 2;
                u32 hw, lw;
                splitpack(acc[mt][nt][half*2], acc[mt][nt][half*2 + 1], hw, lw);
                size_t o = mB + (size_t)d * NH + h;
                *(u32*)&cMh[o] = hw;
                *(u32*)&cMl[o] = lw;
            }
        }
}

// ---------------------------------------------------------------------------
// K2: exclusive prefix over chunks on M planes, in place (batched loads, MLP 8).
// ---------------------------------------------------------------------------
__global__ void k_prefix()
{
    int idx = blockIdx.x * 256 + threadIdx.x;      // < NB*DH/4
    int b = idx / (DH / 4);
    int q = idx - b * (DH / 4);
    size_t p0 = (size_t)b * NCH * DH + (size_t)q * 4;
    float r0 = 0.f, r1 = 0.f, r2 = 0.f, r3 = 0.f;

    #pragma unroll
    for (int half = 0; half < 2; half++) {
        size_t pb = p0 + (size_t)half * 8 * DH;
        uint2 vh[8], vl[8];
        #pragma unroll
        for (int c = 0; c < 8; c++) {
            vh[c] = *(const uint2*)&cMh[pb + (size_t)c * DH];
            vl[c] = *(const uint2*)&cMl[pb + (size_t)c * DH];
        }
        #pragma unroll
        for (int c = 0; c < 8; c++) {
            u32 h0, l0, h1, l1;
            splitpack(r0, r1, h0, l0);
            splitpack(r2, r3, h1, l1);
            size_t p = pb + (size_t)c * DH;
            *(uint2*)&cMh[p] = make_uint2(h0, h1);
            *(uint2*)&cMl[p] = make_uint2(l0, l1);
            float2 a0 = bf2f(vh[c].x), a1 = bf2f(vh[c].y);
            float2 b0 = bf2f(vl[c].x), b1 = bf2f(vl[c].y);
            r0 += a0.x + b0.x; r1 += a0.y + b0.y;
            r2 += a1.x + b1.x; r3 += a1.y + b1.y;
        }
    }
}

// ---------------------------------------------------------------------------
// K3 (mma, pipelined): out = X + diag(1/(j+1)) * ( E@M + tril(S,-1)@X )
// Causal MMA skipping: in intra stages (s>=2), 16x16 k-by-m blocks with
// i_min > j_max are all-zero in S — skip their LDSM + MMA (warp-uniform).
// ---------------------------------------------------------------------------
#define KF_ST  32768
#define KF_AL  8192
#define KF_BH  16384
#define KF_BL  24576
#define KF_TOT (2*KF_ST)

__global__ void __launch_bounds__(256, 1) k_final_mma(const float* __restrict__ bx,
                                                      float* __restrict__ out)
{
    extern __shared__ char sm[];
    u32 smb = smem_u32(sm);
    int tid = threadIdx.x, wid = tid >> 5, ln = tid & 31;
    int ht = blockIdx.x, c = blockIdx.y, b = blockIdx.z;
    int h0 = ht * HT;
    int mw = (wid >> 2) * 64;
    int nw = (wid & 3) * 32;

    size_t eT = (size_t)b * ND * NL + (size_t)c * CK;              // + d*NL
    size_t sT = (size_t)(b * NCH + c) * CK * CK;                   // + i*CK
    size_t mB = (size_t)(b * NCH + c) * DH + h0;                   // + d*NH
    const float* Xg = bx + ((size_t)b * NL + c * CK) * NH + h0;

    float acc[4][4][4];
    #pragma unroll
    for (int i = 0; i < 4; i++)
        #pragma unroll
        for (int j = 0; j < 4; j++)
            #pragma unroll
            for (int k = 0; k < 4; k++) acc[i][j][k] = 0.f;

    // prologue: stage 0 (A = E^T rows d0..31, B = M rows d0..31)
    {
        #pragma unroll
        for (int it = 0; it < 2; it++) {
            int idx = tid + it * 256, r = idx >> 4, c16 = idx & 15;
            u32 off = r * 256 + ((c16 ^ (r & 7)) << 4);
            size_t oa = eT + (size_t)r * NL + c16 * 8;
            cpa(smb + off, cEhT + oa);
            cpa(smb + KF_AL + off, cElT + oa);
            size_t ob = mB + (size_t)r * NH + c16 * 8;
            cpa(smb + KF_BH + off, cMh + ob);
            cpa(smb + KF_BL + off, cMl + ob);
        }
        CP_COMMIT();
    }

    for (int s = 0; s < 6; s++) {
        CP_WAIT0();
        __syncthreads();
        u32 cur = smb + (s & 1) * KF_ST;
        char* nxtp = sm + ((s + 1) & 1) * KF_ST;
        u32 nxt = smb + ((s + 1) & 1) * KF_ST;
        float4 xr[4];
        if (s < 5) {
            int s1 = s + 1;
            #pragma unroll
            for (int it = 0; it < 2; it++) {
                int idx = tid + it * 256, r = idx >> 4, c16 = idx & 15;
                u32 off = r * 256 + ((c16 ^ (r & 7)) << 4);
                const __nv_bfloat16 *ph, *pl;
                if (s1 < 2) {
                    size_t oa = eT + (size_t)(s1 * 32 + r) * NL + c16 * 8;
                    ph = cEhT + oa; pl = cElT + oa;
                } else {
                    size_t oa = sT + (size_t)((s1 - 2) * 32 + r) * CK + c16 * 8;
                    ph = cShT + oa; pl = cSlT + oa;
                }
                cpa(nxt + off, ph);
                cpa(nxt + KF_AL + off, pl);
                if (s1 < 2) {
                    size_t ob = mB + (size_t)(s1 * 32 + r) * NH + c16 * 8;
                    cpa(nxt + KF_BH + off, cMh + ob);
                    cpa(nxt + KF_BL + off, cMl + ob);
                }
            }
            CP_COMMIT();
            if (s1 >= 2) {
                const float* xs = Xg + (size_t)((s1 - 2) * 32) * NH;
                #pragma unroll
                for (int it = 0; it < 2; it++) {
                    int idx = tid + it * 256, rr = idx >> 4, cc = idx & 15;
                    const float* p = xs + (size_t)rr * NH + cc * 8;
                    xr[it*2]     = *(const float4*)p;
                    xr[it*2 + 1] = *(const float4*)(p + 4);
                }
            }
        }

        // compute stage s (skip all-zero causal blocks in intra stages)
        #pragma unroll
        for (int ks = 0; ks < 2; ks++) {
            int gi = (s - 2) * 32 + ks * 16;                // i_min (valid when s>=2)
            bool anyNeed = (s < 2) || (gi <= mw + 63);
            if (!anyNeed) continue;

            u32 ah[4][4], al[4][4], bh[2][4], bl[2][4];
            int q = ln >> 3;
            #pragma unroll
            for (int mt = 0; mt < 4; mt++) {
                bool need = (s < 2) || (gi <= mw + mt * 16 + 15);
                if (!need) continue;
                int r = ks * 16 + (q >> 1) * 8 + (ln & 7);
                int mc = (mw + mt * 16 + (q & 1) * 8) >> 3;
                u32 off = cur + r * 256 + ((mc ^ (r & 7)) << 4);
                ldsm4t(ah[mt], off);
                ldsm4t(al[mt], off + KF_AL);
            }
            #pragma unroll
            for (int nt2 = 0; nt2 < 2; nt2++) {
                int r = ks * 16 + (q & 1) * 8 + (ln & 7);
                int nc = (nw + nt2 * 16 + (q >> 1) * 8) >> 3;
                u32 off = cur + KF_BH + r * 256 + ((nc ^ (r & 7)) << 4);
                ldsm4t(bh[nt2], off);
                ldsm4t(bl[nt2], off + (KF_BL - KF_BH));
            }
            #pragma unroll
            for (int mt = 0; mt < 4; mt++) {
                bool need = (s < 2) || (gi <= mw + mt * 16 + 15);
                if (!need) continue;
                #pragma unroll
                for (int nt2 = 0; nt2 < 2; nt2++) {
                    mma16816(acc[mt][nt2*2],   ah[mt], &bh[nt2][0]);
                    mma16816(acc[mt][nt2*2+1], ah[mt], &bh[nt2][2]);
                    mma16816(acc[mt][nt2*2],   ah[mt], &bl[nt2][0]);
                    mma16816(acc[mt][nt2*2+1], ah[mt], &bl[nt2][2]);
                    mma16816(acc[mt][nt2*2],   al[mt], &bh[nt2][0]);
                    mma16816(acc[mt][nt2*2+1], al[mt], &bh[nt2][2]);
                }
            }
        }

        if (s < 5 && s + 1 >= 2) {
            #pragma unroll
            for (int it = 0; it < 2; it++) {
                int idx = tid + it * 256, rr = idx >> 4, cc = idx & 15;
                float4 v0 = xr[it*2], v1 = xr[it*2 + 1];
                u32 h0w,l0w,h1w,l1w,h2w,l2w,h3w,l3w;
                splitpack(v0.x, v0.y, h0w, l0w); splitpack(v0.z, v0.w, h1w, l1w);
                splitpack(v1.x, v1.y, h2w, l2w); splitpack(v1.z, v1.w, h3w, l3w);
                u32 boff = rr * 256 + ((cc ^ (rr & 7)) << 4);
                *(uint4*)(nxtp + KF_BH + boff) = make_uint4(h0w, h1w, h2w, h3w);
                *(uint4*)(nxtp + KF_BL + boff) = make_uint4(l0w, l1w, l2w, l3w);
            }
        }
    }

    // Epilogue: out = x + (1/(j+1)) * acc
    #pragma unroll
    for (int mt = 0; mt < 4; mt++)
        #pragma unroll
        for (int half = 0; half < 2; half++) {
            int jl = mw + mt * 16 + (ln >> 2) + half * 8;
            float rj = 1.f / (float)(c * CK + jl + 1);
            size_t base = ((size_t)b * NL + c * CK + jl) * NH + h0 + nw + (ln & 3) * 2;
            #pragma unroll
            for (int nt = 0; nt < 4; nt++) {
                float2 x = *(const float2*)(bx + base + nt * 8);
                *(float2*)(out + base + nt * 8) =
                    make_float2(x.x + rj * acc[mt][nt][half*2],
                                x.y + rj * acc[mt][nt][half*2 + 1]);
            }
        }
}

// ---------------------------------------------------------------------------
extern "C" void kernel_launch(void* const* d_in, const int* in_sizes, int n_in,
                              void* d_out, int out_size)
{
    const float* bx = (const float*)d_in[0];   // bert_x [B,L,H] f32
    const void*  x  = d_in[1];                 // x      [B,L]   int32/int64 (auto)
    const float* ae = (const float*)d_in[2];   // ae     [V,D]   f32
    const float* w  = (const float*)d_in[3];   // w      [D,D]   f32
    float* out = (float*)d_out;

    (void)in_sizes; (void)n_in; (void)out_size;

    cudaFuncSetAttribute(k_outer_mma, cudaFuncAttributeMaxDynamicSharedMemorySize, KO_TOT);
    cudaFuncSetAttribute(k_final_mma, cudaFuncAttributeMaxDynamicSharedMemorySize, KF_TOT);

    k_embed    <<<NB * NL / 4, 256>>>(x, ae, w);
    k_scores   <<<dim3(NCH, NB), 256>>>();
    k_outer_mma<<<dim3(NHT, NCH, NB), 256, KO_TOT>>>(bx);
    k_prefix   <<<NB * DH / 1024, 256>>>();
    k_final_mma<<<dim3(NHT, NCH, NB), 256, KF_TOT>>>(bx, out);
}

// round 10
// speedup vs baseline: 1.1581x; 1.1581x over previous
#include <cuda_runtime.h>
#include <cuda_bf16.h>
#include <cstdint>

// Problem shape
#define NB  16
#define NL  2048
#define NH  768
#define ND  64
#define CK  128
#define NCH (NL/CK)       // 16
#define HT  128
#define NHT (NH/HT)       // 6
#define DH  (ND*NH)       // 49152

typedef unsigned int u32;

// Scratch planes (bf16 hi/lo; ~92 MB total)
#define NE (NB*NL*ND)
__device__ __align__(16) __nv_bfloat16 cEh [NE], cEl [NE];                   // E  [t][d]
__device__ __align__(16) __nv_bfloat16 cFh [NE], cFl [NE];                   // Fp [t][d]
__device__ __align__(16) __nv_bfloat16 cEhT[NB*ND*NL],    cElT[NB*ND*NL];    // E^T [b][d][j]
__device__ __align__(16) __nv_bfloat16 cShT[NB*NCH*CK*CK],cSlT[NB*NCH*CK*CK];// S^T [i][j] masked
__device__ __align__(16) __nv_bfloat16 cMh [NB*NCH*DH],   cMl [NB*NCH*DH];   // M  [d][h]

// ---------------------------------------------------------------------------
// helpers
// ---------------------------------------------------------------------------
__device__ __forceinline__ u32 smem_u32(const void* p) {
    u32 a;
    asm("{ .reg .u64 t; cvta.to.shared.u64 t, %1; cvt.u32.u64 %0, t; }" : "=r"(a) : "l"(p));
    return a;
}
__device__ __forceinline__ u32 packbf(__nv_bfloat16 a, __nv_bfloat16 b) {
    __nv_bfloat162 t(a, b);
    return *reinterpret_cast<u32*>(&t);
}
__device__ __forceinline__ void splitpack(float a, float b, u32& hi, u32& lo) {
    __nv_bfloat16 ah = __float2bfloat16(a);
    __nv_bfloat16 bh = __float2bfloat16(b);
    __nv_bfloat16 al = __float2bfloat16(a - __bfloat162float(ah));
    __nv_bfloat16 bl = __float2bfloat16(b - __bfloat162float(bh));
    hi = packbf(ah, bh);
    lo = packbf(al, bl);
}
__device__ __forceinline__ float2 bf2f(u32 w) {
    __nv_bfloat162 t = *reinterpret_cast<__nv_bfloat162*>(&w);
    return make_float2(__bfloat162float(t.x), __bfloat162float(t.y));
}
__device__ __forceinline__ void cpa(u32 dst, const void* src) {
    asm volatile("cp.async.ca.shared.global [%0], [%1], 16;" :: "r"(dst), "l"(src));
}
#define CP_COMMIT() asm volatile("cp.async.commit_group;" ::: "memory")
#define CP_WAIT0()  asm volatile("cp.async.wait_group 0;" ::: "memory")

__device__ __forceinline__ void ldsm4t(u32* r, u32 addr) {
    asm volatile("ldmatrix.sync.aligned.m8n8.x4.trans.shared.b16 {%0,%1,%2,%3}, [%4];"
        : "=r"(r[0]), "=r"(r[1]), "=r"(r[2]), "=r"(r[3]) : "r"(addr));
}
__device__ __forceinline__ void mma16816(float* d, const u32* a, const u32* b) {
    asm volatile("mma.sync.aligned.m16n8k16.row.col.f32.bf16.bf16.f32 "
        "{%0,%1,%2,%3}, {%4,%5,%6,%7}, {%8,%9}, {%0,%1,%2,%3};"
        : "+f"(d[0]), "+f"(d[1]), "+f"(d[2]), "+f"(d[3])
        : "r"(a[0]), "r"(a[1]), "r"(a[2]), "r"(a[3]), "r"(b[0]), "r"(b[1]));
}

// ---------------------------------------------------------------------------
// K0: embedding gather + Fp = (l+1) * E @ w ; emits E/Fp hi-lo planes
// ---------------------------------------------------------------------------
__global__ void k_embed(const void* __restrict__ xraw,
                        const float* __restrict__ ae,
                        const float* __restrict__ w)
{
    __shared__ float sW[ND][ND];
    __shared__ float sE[4][ND];

    int tid = threadIdx.x;

    // Detect index dtype: int64 (odd 32-bit words all zero) vs int32.
    const int* xi = (const int*)xraw;
    int oddw = xi[((tid & 63) << 1) + 1];
    int is64 = __syncthreads_and(oddw == 0);

    for (int i = tid; i < ND * ND; i += 256)
        ((float*)sW)[i] = w[i];

    int q = tid >> 6;
    int d = tid & 63;
    int t = blockIdx.x * 4 + q;
    int l = t & (NL - 1);

    long long v;
    if (is64) v = ((const long long*)xraw)[t];
    else      v = (long long)xi[t];

    float e = ae[v * ND + d];
    sE[q][d] = e;
    size_t td = (size_t)t * ND + d;
    {
        float ep = __shfl_xor_sync(0xffffffffu, e, 1);
        if (!(d & 1)) {
            u32 hw, lw; splitpack(e, ep, hw, lw);
            *(u32*)&cEh[td] = hw;
            *(u32*)&cEl[td] = lw;
        }
    }
    __syncthreads();

    float acc = 0.f;
    #pragma unroll
    for (int k = 0; k < ND; k++)
        acc += sE[q][k] * sW[k][d];

    float fp = (float)(l + 1) * acc;
    {
        float fpp = __shfl_xor_sync(0xffffffffu, fp, 1);
        if (!(d & 1)) {
            u32 hw, lw; splitpack(fp, fpp, hw, lw);
            *(u32*)&cFh[td] = hw;
            *(u32*)&cFl[td] = lw;
        }
    }
}

// ---------------------------------------------------------------------------
// K1b: intra-chunk scores (scalar fp32); emits masked S^T planes + E^T planes
// ---------------------------------------------------------------------------
__global__ void k_scores()
{
    __shared__ float sEt[32][CK];
    __shared__ float sFt[32][CK];

    int tid = threadIdx.x;
    int c = blockIdx.x, b = blockIdx.y;

    size_t base = ((size_t)b * NL + c * CK) * ND;
    int tj = tid & 15;
    int ti = tid >> 4;

    float acc[8][8];
    #pragma unroll
    for (int r = 0; r < 8; r++)
        #pragma unroll
        for (int s = 0; s < 8; s++) acc[r][s] = 0.f;

    for (int dt = 0; dt < ND; dt += 32) {
        int f4 = tid & 7, r0 = tid >> 3;
        #pragma unroll
        for (int rep = 0; rep < 4; rep++) {
            int row = r0 + rep * 32;
            size_t o = base + (size_t)row * ND + dt + f4 * 4;
            uint2 vh = *(const uint2*)(cEh + o);
            uint2 vl = *(const uint2*)(cEl + o);
            float2 p0 = bf2f(vh.x), p1 = bf2f(vh.y), q0 = bf2f(vl.x), q1 = bf2f(vl.y);
            sEt[f4*4+0][row] = p0.x + q0.x; sEt[f4*4+1][row] = p0.y + q0.y;
            sEt[f4*4+2][row] = p1.x + q1.x; sEt[f4*4+3][row] = p1.y + q1.y;
            uint2 uh = *(const uint2*)(cFh + o);
            uint2 ul = *(const uint2*)(cFl + o);
            float2 a0 = bf2f(uh.x), a1 = bf2f(uh.y), b0 = bf2f(ul.x), b1 = bf2f(ul.y);
            sFt[f4*4+0][row] = a0.x + b0.x; sFt[f4*4+1][row] = a0.y + b0.y;
            sFt[f4*4+2][row] = a1.x + b1.x; sFt[f4*4+3][row] = a1.y + b1.y;
        }
        __syncthreads();

        // emit E^T planes for this d-slab: rows d = dt+r, 128 j cols
        {
            int r = tid >> 3, c8 = tid & 7;
            float4 v0 = *(const float4*)&sEt[r][c8*16];
            float4 v1 = *(const float4*)&sEt[r][c8*16 + 4];
            float4 v2 = *(const float4*)&sEt[r][c8*16 + 8];
            float4 v3 = *(const float4*)&sEt[r][c8*16 + 12];
            u32 h0,l0,h1,l1,h2,l2,h3,l3,h4,l4,h5,l5,h6,l6,h7,l7;
            splitpack(v0.x, v0.y, h0, l0); splitpack(v0.z, v0.w, h1, l1);
            splitpack(v1.x, v1.y, h2, l2); splitpack(v1.z, v1.w, h3, l3);
            splitpack(v2.x, v2.y, h4, l4); splitpack(v2.z, v2.w, h5, l5);
            splitpack(v3.x, v3.y, h6, l6); splitpack(v3.z, v3.w, h7, l7);
            size_t o = (size_t)b * ND * NL + (size_t)(dt + r) * NL + (size_t)c * CK + c8 * 16;
            *(uint4*)(cEhT + o)     = make_uint4(h0, h1, h2, h3);
            *(uint4*)(cEhT + o + 8) = make_uint4(h4, h5, h6, h7);
            *(uint4*)(cElT + o)     = make_uint4(l0, l1, l2, l3);
            *(uint4*)(cElT + o + 8) = make_uint4(l4, l5, l6, l7);
        }

        #pragma unroll 8
        for (int kk = 0; kk < 32; kk++) {
            float4 a0 = *(const float4*)&sEt[kk][tj*8];
            float4 a1 = *(const float4*)&sEt[kk][tj*8 + 4];
            float4 b0 = *(const float4*)&sFt[kk][ti*8];
            float4 b1 = *(const float4*)&sFt[kk][ti*8 + 4];
            float av[8] = {a0.x,a0.y,a0.z,a0.w,a1.x,a1.y,a1.z,a1.w};
            float bv[8] = {b0.x,b0.y,b0.z,b0.w,b1.x,b1.y,b1.z,b1.w};
            #pragma unroll
            for (int r = 0; r < 8; r++)
                #pragma unroll
                for (int s = 0; s < 8; s++)
                    acc[r][s] += av[r] * bv[s];
        }
        __syncthreads();
    }

    // emit masked S^T planes: row i, cols j
    size_t ST0 = (size_t)(b * NCH + c) * CK * CK;
    #pragma unroll
    for (int s = 0; s < 8; s++) {
        int i = ti * 8 + s;
        u32 hw[4], lw[4];
        #pragma unroll
        for (int p = 0; p < 4; p++) {
            int j0 = tj * 8 + 2 * p;
            float a  = (i < j0)     ? acc[2*p][s]     : 0.f;
            float bb = (i < j0 + 1) ? acc[2*p + 1][s] : 0.f;
            splitpack(a, bb, hw[p], lw[p]);
        }
        size_t o = ST0 + (size_t)i * CK + tj * 8;
        *(uint4*)(cShT + o) = make_uint4(hw[0], hw[1], hw[2], hw[3]);
        *(uint4*)(cSlT + o) = make_uint4(lw[0], lw[1], lw[2], lw[3]);
    }
}

// ---------------------------------------------------------------------------
// K1a (mma, pipelined): M[d][h] = sum_i Fp[i][d] * X[i][h]; 4 stages of k=32
// 2 CTAs/SM for stage-boundary latency overlap.
// ---------------------------------------------------------------------------
#define KO_ST  24576
#define KO_AL  4096
#define KO_BH  8192
#define KO_BL  16384
#define KO_TOT (2*KO_ST)

__global__ void __launch_bounds__(256, 2) k_outer_mma(const float* __restrict__ bx)
{
    extern __shared__ char sm[];
    u32 smb = smem_u32(sm);
    int tid = threadIdx.x, wid = tid >> 5, ln = tid & 31;
    int ht = blockIdx.x, c = blockIdx.y, b = blockIdx.z;
    int h0 = ht * HT;
    int mw = (wid >> 2) * 32;
    int nw = (wid & 3) * 32;

    size_t fB = ((size_t)b * NL + c * CK) * ND;
    const float* Xg = bx + ((size_t)b * NL + c * CK) * NH + h0;

    float acc[2][4][4];
    #pragma unroll
    for (int i = 0; i < 2; i++)
        #pragma unroll
        for (int j = 0; j < 4; j++)
            #pragma unroll
            for (int k = 0; k < 4; k++) acc[i][j][k] = 0.f;

    // prologue: stage 0
    {
        int r = tid >> 3, c8 = tid & 7;
        u32 off = r * 128 + ((c8 ^ (r & 7)) << 4);
        size_t o = fB + (size_t)r * ND + c8 * 8;
        cpa(smb + off, cFh + o);
        cpa(smb + KO_AL + off, cFl + o);
        CP_COMMIT();
        #pragma unroll
        for (int it = 0; it < 2; it++) {
            int idx = tid + it * 256, rr = idx >> 4, cc = idx & 15;
            const float* p = Xg + (size_t)rr * NH + cc * 8;
            float4 v0 = *(const float4*)p;
            float4 v1 = *(const float4*)(p + 4);
            u32 h0w,l0w,h1w,l1w,h2w,l2w,h3w,l3w;
            splitpack(v0.x, v0.y, h0w, l0w); splitpack(v0.z, v0.w, h1w, l1w);
            splitpack(v1.x, v1.y, h2w, l2w); splitpack(v1.z, v1.w, h3w, l3w);
            u32 boff = rr * 256 + ((cc ^ (rr & 7)) << 4);
            *(uint4*)(sm + KO_BH + boff) = make_uint4(h0w, h1w, h2w, h3w);
            *(uint4*)(sm + KO_BL + boff) = make_uint4(l0w, l1w, l2w, l3w);
        }
    }

    for (int s = 0; s < 4; s++) {
        CP_WAIT0();
        __syncthreads();
        u32 cur = smb + (s & 1) * KO_ST;
        char* nxtp = sm + ((s + 1) & 1) * KO_ST;
        u32 nxt = smb + ((s + 1) & 1) * KO_ST;
        float4 xr[4];
        if (s < 3) {
            int s1 = s + 1;
            int r = tid >> 3, c8 = tid & 7;
            u32 off = r * 128 + ((c8 ^ (r & 7)) << 4);
            size_t o = fB + (size_t)(s1 * 32 + r) * ND + c8 * 8;
            cpa(nxt + off, cFh + o);
            cpa(nxt + KO_AL + off, cFl + o);
            CP_COMMIT();
            const float* xs = Xg + (size_t)(s1 * 32) * NH;
            #pragma unroll
            for (int it = 0; it < 2; it++) {
                int idx = tid + it * 256, rr = idx >> 4, cc = idx & 15;
                const float* p = xs + (size_t)rr * NH + cc * 8;
                xr[it*2]     = *(const float4*)p;
                xr[it*2 + 1] = *(const float4*)(p + 4);
            }
        }

        #pragma unroll
        for (int ks = 0; ks < 2; ks++) {
            u32 ah[2][4], al[2][4], bh[2][4], bl[2][4];
            int q = ln >> 3;
            #pragma unroll
            for (int mt = 0; mt < 2; mt++) {
                int r = ks * 16 + (q >> 1) * 8 + (ln & 7);
                int mc = (mw + mt * 16 + (q & 1) * 8) >> 3;
                u32 off = cur + r * 128 + ((mc ^ (r & 7)) << 4);
                ldsm4t(ah[mt], off);
                ldsm4t(al[mt], off + KO_AL);
            }
            #pragma unroll
            for (int nt2 = 0; nt2 < 2; nt2++) {
                int r = ks * 16 + (q & 1) * 8 + (ln & 7);
                int nc = (nw + nt2 * 16 + (q >> 1) * 8) >> 3;
                u32 off = cur + KO_BH + r * 256 + ((nc ^ (r & 7)) << 4);
                ldsm4t(bh[nt2], off);
                ldsm4t(bl[nt2], off + (KO_BL - KO_BH));
            }
            #pragma unroll
            for (int mt = 0; mt < 2; mt++)
                #pragma unroll
                for (int nt2 = 0; nt2 < 2; nt2++) {
                    mma16816(acc[mt][nt2*2],   ah[mt], &bh[nt2][0]);
                    mma16816(acc[mt][nt2*2+1], ah[mt], &bh[nt2][2]);
                    mma16816(acc[mt][nt2*2],   ah[mt], &bl[nt2][0]);
                    mma16816(acc[mt][nt2*2+1], ah[mt], &bl[nt2][2]);
                    mma16816(acc[mt][nt2*2],   al[mt], &bh[nt2][0]);
                    mma16816(acc[mt][nt2*2+1], al[mt], &bh[nt2][2]);
                }
        }

        if (s < 3) {
            #pragma unroll
            for (int it = 0; it < 2; it++) {
                int idx = tid + it * 256, rr = idx >> 4, cc = idx & 15;
                float4 v0 = xr[it*2], v1 = xr[it*2 + 1];
                u32 h0w,l0w,h1w,l1w,h2w,l2w,h3w,l3w;
                splitpack(v0.x, v0.y, h0w, l0w); splitpack(v0.z, v0.w, h1w, l1w);
                splitpack(v1.x, v1.y, h2w, l2w); splitpack(v1.z, v1.w, h3w, l3w);
                u32 boff = rr * 256 + ((cc ^ (rr & 7)) << 4);
                *(uint4*)(nxtp + KO_BH + boff) = make_uint4(h0w, h1w, h2w, h3w);
                *(uint4*)(nxtp + KO_BL + boff) = make_uint4(l0w, l1w, l2w, l3w);
            }
        }
    }

    // epilogue: write M planes (hi/lo)
    size_t mB = (size_t)(b * NCH + c) * DH;
    #pragma unroll
    for (int mt = 0; mt < 2; mt++)
        #pragma unroll
        for (int half = 0; half < 2; half++) {
            int d = mw + mt * 16 + (ln >> 2) + half * 8;
            #pragma unroll
            for (int nt = 0; nt < 4; nt++) {
                int h = h0 + nw + nt * 8 + (ln & 3) * 2;
                u32 hw, lw;
                splitpack(acc[mt][nt][half*2], acc[mt][nt][half*2 + 1], hw, lw);
                size_t o = mB + (size_t)d * NH + h;
                *(u32*)&cMh[o] = hw;
                *(u32*)&cMl[o] = lw;
            }
        }
}

// ---------------------------------------------------------------------------
// K2: exclusive prefix over chunks on M planes, in place (batched loads, MLP 8).
// ---------------------------------------------------------------------------
__global__ void k_prefix()
{
    int idx = blockIdx.x * 256 + threadIdx.x;      // < NB*DH/4
    int b = idx / (DH / 4);
    int q = idx - b * (DH / 4);
    size_t p0 = (size_t)b * NCH * DH + (size_t)q * 4;
    float r0 = 0.f, r1 = 0.f, r2 = 0.f, r3 = 0.f;

    #pragma unroll
    for (int half = 0; half < 2; half++) {
        size_t pb = p0 + (size_t)half * 8 * DH;
        uint2 vh[8], vl[8];
        #pragma unroll
        for (int c = 0; c < 8; c++) {
            vh[c] = *(const uint2*)&cMh[pb + (size_t)c * DH];
            vl[c] = *(const uint2*)&cMl[pb + (size_t)c * DH];
        }
        #pragma unroll
        for (int c = 0; c < 8; c++) {
            u32 h0, l0, h1, l1;
            splitpack(r0, r1, h0, l0);
            splitpack(r2, r3, h1, l1);
            size_t p = pb + (size_t)c * DH;
            *(uint2*)&cMh[p] = make_uint2(h0, h1);
            *(uint2*)&cMl[p] = make_uint2(l0, l1);
            float2 a0 = bf2f(vh[c].x), a1 = bf2f(vh[c].y);
            float2 b0 = bf2f(vl[c].x), b1 = bf2f(vl[c].y);
            r0 += a0.x + b0.x; r1 += a0.y + b0.y;
            r2 += a1.x + b1.x; r3 += a1.y + b1.y;
        }
    }
}

// ---------------------------------------------------------------------------
// K3 (mma, pipelined): out = X + diag(1/(j+1)) * ( E@M + tril(S,-1)@X )
// 6 stages of k=32; 2 CTAs/SM for stage-boundary latency overlap.
// ---------------------------------------------------------------------------
#define KF_ST  32768
#define KF_AL  8192
#define KF_BH  16384
#define KF_BL  24576
#define KF_TOT (2*KF_ST)

__global__ void __launch_bounds__(256, 2) k_final_mma(const float* __restrict__ bx,
                                                      float* __restrict__ out)
{
    extern __shared__ char sm[];
    u32 smb = smem_u32(sm);
    int tid = threadIdx.x, wid = tid >> 5, ln = tid & 31;
    int ht = blockIdx.x, c = blockIdx.y, b = blockIdx.z;
    int h0 = ht * HT;
    int mw = (wid >> 2) * 64;
    int nw = (wid & 3) * 32;

    size_t eT = (size_t)b * ND * NL + (size_t)c * CK;              // + d*NL
    size_t sT = (size_t)(b * NCH + c) * CK * CK;                   // + i*CK
    size_t mB = (size_t)(b * NCH + c) * DH + h0;                   // + d*NH
    const float* Xg = bx + ((size_t)b * NL + c * CK) * NH + h0;

    float acc[4][4][4];
    #pragma unroll
    for (int i = 0; i < 4; i++)
        #pragma unroll
        for (int j = 0; j < 4; j++)
            #pragma unroll
            for (int k = 0; k < 4; k++) acc[i][j][k] = 0.f;

    // prologue: stage 0 (A = E^T rows d0..31, B = M rows d0..31)
    {
        #pragma unroll
        for (int it = 0; it < 2; it++) {
            int idx = tid + it * 256, r = idx >> 4, c16 = idx & 15;
            u32 off = r * 256 + ((c16 ^ (r & 7)) << 4);
            size_t oa = eT + (size_t)r * NL + c16 * 8;
            cpa(smb + off, cEhT + oa);
            cpa(smb + KF_AL + off, cElT + oa);
            size_t ob = mB + (size_t)r * NH + c16 * 8;
            cpa(smb + KF_BH + off, cMh + ob);
            cpa(smb + KF_BL + off, cMl + ob);
        }
        CP_COMMIT();
    }

    for (int s = 0; s < 6; s++) {
        CP_WAIT0();
        __syncthreads();
        u32 cur = smb + (s & 1) * KF_ST;
        char* nxtp = sm + ((s + 1) & 1) * KF_ST;
        u32 nxt = smb + ((s + 1) & 1) * KF_ST;
        float4 xr[4];
        if (s < 5) {
            int s1 = s + 1;
            #pragma unroll
            for (int it = 0; it < 2; it++) {
                int idx = tid + it * 256, r = idx >> 4, c16 = idx & 15;
                u32 off = r * 256 + ((c16 ^ (r & 7)) << 4);
                const __nv_bfloat16 *ph, *pl;
                if (s1 < 2) {
                    size_t oa = eT + (size_t)(s1 * 32 + r) * NL + c16 * 8;
                    ph = cEhT + oa; pl = cElT + oa;
                } else {
                    size_t oa = sT + (size_t)((s1 - 2) * 32 + r) * CK + c16 * 8;
                    ph = cShT + oa; pl = cSlT + oa;
                }
                cpa(nxt + off, ph);
                cpa(nxt + KF_AL + off, pl);
                if (s1 < 2) {
                    size_t ob = mB + (size_t)(s1 * 32 + r) * NH + c16 * 8;
                    cpa(nxt + KF_BH + off, cMh + ob);
                    cpa(nxt + KF_BL + off, cMl + ob);
                }
            }
            CP_COMMIT();
            if (s1 >= 2) {
                const float* xs = Xg + (size_t)((s1 - 2) * 32) * NH;
                #pragma unroll
                for (int it = 0; it < 2; it++) {
                    int idx = tid + it * 256, rr = idx >> 4, cc = idx & 15;
                    const float* p = xs + (size_t)rr * NH + cc * 8;
                    xr[it*2]     = *(const float4*)p;
                    xr[it*2 + 1] = *(const float4*)(p + 4);
                }
            }
        }

        // compute stage s
        #pragma unroll
        for (int ks = 0; ks < 2; ks++) {
            u32 ah[4][4], al[4][4], bh[2][4], bl[2][4];
            int q = ln >> 3;
            #pragma unroll
            for (int mt = 0; mt < 4; mt++) {
                int r = ks * 16 + (q >> 1) * 8 + (ln & 7);
                int mc = (mw + mt * 16 + (q & 1) * 8) >> 3;
                u32 off = cur + r * 256 + ((mc ^ (r & 7)) << 4);
                ldsm4t(ah[mt], off);
                ldsm4t(al[mt], off + KF_AL);
            }
            #pragma unroll
            for (int nt2 = 0; nt2 < 2; nt2++) {
                int r = ks * 16 + (q & 1) * 8 + (ln & 7);
                int nc = (nw + nt2 * 16 + (q >> 1) * 8) >> 3;
                u32 off = cur + KF_BH + r * 256 + ((nc ^ (r & 7)) << 4);
                ldsm4t(bh[nt2], off);
                ldsm4t(bl[nt2], off + (KF_BL - KF_BH));
            }
            #pragma unroll
            for (int mt = 0; mt < 4; mt++)
                #pragma unroll
                for (int nt2 = 0; nt2 < 2; nt2++) {
                    mma16816(acc[mt][nt2*2],   ah[mt], &bh[nt2][0]);
                    mma16816(acc[mt][nt2*2+1], ah[mt], &bh[nt2][2]);
                    mma16816(acc[mt][nt2*2],   ah[mt], &bl[nt2][0]);
                    mma16816(acc[mt][nt2*2+1], ah[mt], &bl[nt2][2]);
                    mma16816(acc[mt][nt2*2],   al[mt], &bh[nt2][0]);
                    mma16816(acc[mt][nt2*2+1], al[mt], &bh[nt2][2]);
                }
        }

        if (s < 5 && s + 1 >= 2) {
            #pragma unroll
            for (int it = 0; it < 2; it++) {
                int idx = tid + it * 256, rr = idx >> 4, cc = idx & 15;
                float4 v0 = xr[it*2], v1 = xr[it*2 + 1];
                u32 h0w,l0w,h1w,l1w,h2w,l2w,h3w,l3w;
                splitpack(v0.x, v0.y, h0w, l0w); splitpack(v0.z, v0.w, h1w, l1w);
                splitpack(v1.x, v1.y, h2w, l2w); splitpack(v1.z, v1.w, h3w, l3w);
                u32 boff = rr * 256 + ((cc ^ (rr & 7)) << 4);
                *(uint4*)(nxtp + KF_BH + boff) = make_uint4(h0w, h1w, h2w, h3w);
                *(uint4*)(nxtp + KF_BL + boff) = make_uint4(l0w, l1w, l2w, l3w);
            }
        }
    }

    // Epilogue: out = x + (1/(j+1)) * acc
    #pragma unroll
    for (int mt = 0; mt < 4; mt++)
        #pragma unroll
        for (int half = 0; half < 2; half++) {
            int jl = mw + mt * 16 + (ln >> 2) + half * 8;
            float rj = 1.f / (float)(c * CK + jl + 1);
            size_t base = ((size_t)b * NL + c * CK + jl) * NH + h0 + nw + (ln & 3) * 2;
            #pragma unroll
            for (int nt = 0; nt < 4; nt++) {
                float2 x = *(const float2*)(bx + base + nt * 8);
                *(float2*)(out + base + nt * 8) =
                    make_float2(x.x + rj * acc[mt][nt][half*2],
                                x.y + rj * acc[mt][nt][half*2 + 1]);
            }
        }
}

// ---------------------------------------------------------------------------
extern "C" void kernel_launch(void* const* d_in, const int* in_sizes, int n_in,
                              void* d_out, int out_size)
{
    const float* bx = (const float*)d_in[0];   // bert_x [B,L,H] f32
    const void*  x  = d_in[1];                 // x      [B,L]   int32/int64 (auto)
    const float* ae = (const float*)d_in[2];   // ae     [V,D]   f32
    const float* w  = (const float*)d_in[3];   // w      [D,D]   f32
    float* out = (float*)d_out;

    (void)in_sizes; (void)n_in; (void)out_size;

    cudaFuncSetAttribute(k_outer_mma, cudaFuncAttributeMaxDynamicSharedMemorySize, KO_TOT);
    cudaFuncSetAttribute(k_final_mma, cudaFuncAttributeMaxDynamicSharedMemorySize, KF_TOT);

    k_embed    <<<NB * NL / 4, 256>>>(x, ae, w);
    k_scores   <<<dim3(NCH, NB), 256>>>();
    k_outer_mma<<<dim3(NHT, NCH, NB), 256, KO_TOT>>>(bx);
    k_prefix   <<<NB * DH / 1024, 256>>>();
    k_final_mma<<<dim3(NHT, NCH, NB), 256, KF_TOT>>>(bx, out);
}